// round 17
// baseline (speedup 1.0000x reference)
#include <cuda_runtime.h>

#define BATCH 128
#define SEQ   512
#define DIM   768
#define MAXC  64

__device__ int g_sidx[BATCH * MAXC];

// ---------------- K1: per-batch compaction (128 CTAs x 128 threads) ----------------
__global__ __launch_bounds__(128)
void compact_kernel(const int* __restrict__ cls) {
    __shared__ int sidx[MAXC];
    __shared__ int wtot[4];

    const int b    = blockIdx.x;
    const int tid  = threadIdx.x;
    const int lane = tid & 31;
    const int warp = tid >> 5;

    if (tid < MAXC) sidx[tid] = -1;

    const int4 cv = reinterpret_cast<const int4*>(cls + (size_t)b * SEQ)[tid];
    const int f0 = (cv.x != 0), f1 = (cv.y != 0), f2 = (cv.z != 0), f3 = (cv.w != 0);
    const int cnt = f0 + f1 + f2 + f3;

    int s = cnt;
    #pragma unroll
    for (int off = 1; off < 32; off <<= 1) {
        int n = __shfl_up_sync(0xffffffffu, s, off);
        if (lane >= off) s += n;
    }
    const int excl = s - cnt;
    if (lane == 31) wtot[warp] = s;
    __syncthreads();

    int base = 0;
    #pragma unroll
    for (int i = 0; i < 4; i++) base += (i < warp) ? wtot[i] : 0;

    {
        int r = base + excl;
        const int p = tid * 4;
        if (f0) { if (r < MAXC) sidx[r] = p;     r++; }
        if (f1) { if (r < MAXC) sidx[r] = p + 1; r++; }
        if (f2) { if (r < MAXC) sidx[r] = p + 2; r++; }
        if (f3) { if (r < MAXC) sidx[r] = p + 3; }
    }
    __syncthreads();

    if (tid < MAXC) g_sidx[b * MAXC + tid] = sidx[tid];
}

// ---------------- K2: one rank per warp (2048 CTAs x 128 threads) ----------------
__global__ __launch_bounds__(128, 16)
void dot_kernel(const float* __restrict__ enc,
                const float* __restrict__ W,
                const float* __restrict__ bias,
                float* __restrict__ out) {
    __shared__ float sW[DIM];

    const int tid  = threadIdx.x;
    const int lane = tid & 31;
    const int warp = tid >> 5;
    const int gw   = blockIdx.x * 4 + warp;   // 8192 warps: one per (batch, rank)
    const int b    = gw >> 6;
    const int r    = gw & 63;

    // Critical dependency first: this warp's gather index (converged L2 load).
    const int p = g_sidx[b * MAXC + r];

    // Stage W to shared (independent; overlaps the idx load). 6 floats/thread.
    #pragma unroll
    for (int i = 0; i < 6; i++) sW[tid + i * 128] = W[tid + i * 128];

    const float bv = bias[0];

    // Issue the 6 gather LDG.128 immediately (before the barrier) so they are
    // in flight while W staging completes.
    float4 a0, a1, a2, a3, a4, a5;
    if (p >= 0) {
        const float4* ra = reinterpret_cast<const float4*>(enc + ((size_t)b * SEQ + p) * DIM);
        a0 = ra[lane +   0];
        a1 = ra[lane +  32];
        a2 = ra[lane +  64];
        a3 = ra[lane +  96];
        a4 = ra[lane + 128];
        a5 = ra[lane + 160];
    }
    __syncthreads();

    float acc = 0.0f;
    if (p >= 0) {
        const float4* w4 = reinterpret_cast<const float4*>(sW);
        float4 w;
        w = w4[lane +   0]; acc += a0.x*w.x + a0.y*w.y + a0.z*w.z + a0.w*w.w;
        w = w4[lane +  32]; acc += a1.x*w.x + a1.y*w.y + a1.z*w.z + a1.w*w.w;
        w = w4[lane +  64]; acc += a2.x*w.x + a2.y*w.y + a2.z*w.z + a2.w*w.w;
        w = w4[lane +  96]; acc += a3.x*w.x + a3.y*w.y + a3.z*w.z + a3.w*w.w;
        w = w4[lane + 128]; acc += a4.x*w.x + a4.y*w.y + a4.z*w.z + a4.w*w.w;
        w = w4[lane + 160]; acc += a5.x*w.x + a5.y*w.y + a5.z*w.z + a5.w*w.w;
    }

    #pragma unroll
    for (int off = 16; off > 0; off >>= 1)
        acc += __shfl_down_sync(0xffffffffu, acc, off);

    if (lane == 0)
        out[b * MAXC + r] = 1.0f / (1.0f + __expf(-(acc + bv)));
}

extern "C" void kernel_launch(void* const* d_in, const int* in_sizes, int n_in,
                              void* d_out, int out_size) {
    const float* enc  = (const float*)d_in[0];
    const float* W    = (const float*)d_in[1];
    const float* bias = (const float*)d_in[2];
    const int*   cls  = (const int*)d_in[3];
    float* out = (float*)d_out;

    compact_kernel<<<BATCH, 128>>>(cls);
    dot_kernel<<<BATCH * MAXC / 4, 128>>>(enc, W, bias, out);
}